// round 3
// baseline (speedup 1.0000x reference)
#include <cuda_runtime.h>
#include <cuda_bf16.h>
#include <math.h>

// Problem shape (fixed by the dataset): x = [4, 32, 4096, 128] fp32.
#define SEQ     4096
#define HDIM    128
#define HALF    (HDIM / 2)          // 64 rotation pairs per row
#define F4_ROW  (HDIM / 4)          // 32 float4 per row (2 pairs per float4)
#define BH      (4 * 32)            // 128 batch*head slices
#define SLICE   (SEQ * F4_ROW)      // float4 count per bh-slice = 131072

// cos/sin table: one float4 (cos0, sin0, cos1, sin1) per (seq, float4-in-row).
// 4096 * 32 * 16 B = 2 MiB static device scratch (no allocation).
__device__ float4 g_tab[SEQ * F4_ROW];

// ---------------------------------------------------------------------------
// Position loader with dtype sniffing. token_positions is int64 in the
// reference, but the harness may have materialized it as int32 or float32.
// Signatures on the raw 32-bit words (positions are small non-negative ints):
//   int64 : odd words (high halves) are all zero
//   int32 : words are small ints (< 2^24)
//   float32: words carry an exponent (>= 2^24 bit patterns for values >= ~1)
// ---------------------------------------------------------------------------
__device__ __forceinline__ double load_pos(const void* p, int s) {
    const unsigned int* w = (const unsigned int*)p;
    // int64 little-endian: high words of first few elements are zero while
    // at least one low word is nonzero.
    bool hi_zero = (w[1] == 0u) & (w[3] == 0u) & (w[5] == 0u) & (w[7] == 0u);
    bool lo_some = (w[0] | w[2] | w[4] | w[6]) != 0u;
    if (hi_zero && (lo_some || (w[8] | w[9]) == 0u)) {
        return (double)((const long long*)p)[s];
    }
    // Distinguish int32 vs float32: small ints have tiny bit patterns;
    // float32 values >= 1.0 have patterns >= 0x3F800000.
    bool small_ints = (w[1] < (1u << 24)) & (w[2] < (1u << 24)) &
                      (w[3] < (1u << 24));
    if (small_ints) return (double)((const int*)p)[s];
    return (double)((const float*)p)[s];
}

__device__ __forceinline__ float reduce_2pi(double a) {
    const double INV_2PI = 0.15915494309189535;
    const double TWO_PI  = 6.283185307179586;
    double k = rint(a * INV_2PI);
    return (float)(a - k * TWO_PI);
}

// ---------------------------------------------------------------------------
// Kernel 1: build the cos/sin table. 131072 threads, a few us.
// Angle in double, range-reduced by 2*pi, then fp32 sincos on the residual.
// ---------------------------------------------------------------------------
__global__ void rope_build_table(const void* __restrict__ pos) {
    int t = blockIdx.x * blockDim.x + threadIdx.x;
    if (t >= SEQ * F4_ROW) return;
    int s = t >> 5;          // seq index
    int j = t & 31;          // float4 index within row -> pairs 2j, 2j+1
    double p = load_pos(pos, s);

    const double LOG2_THETA = 13.287712379549449;   // log2(10000)
    int i0 = 2 * j;
    int i1 = 2 * j + 1;
    // inv_freq_i = theta^(-i/64) = 2^(-(i/64) * log2(theta))
    double f0 = exp2(-((double)i0 / (double)HALF) * LOG2_THETA);
    double f1 = exp2(-((double)i1 / (double)HALF) * LOG2_THETA);

    float a0 = reduce_2pi(p * f0);
    float a1 = reduce_2pi(p * f1);

    float s0, c0, s1, c1;
    sincosf(a0, &s0, &c0);
    sincosf(a1, &s1, &c1);

    g_tab[t] = make_float4(c0, s0, c1, s1);
}

// ---------------------------------------------------------------------------
// Kernel 2: streaming rotate. One thread per float4 of a single bh-slice;
// table entry loaded once into registers, reused across all 128 bh slices.
// Every warp iteration touches 512 contiguous bytes -> perfect coalescing.
// ---------------------------------------------------------------------------
__global__ __launch_bounds__(256) void rope_apply(
    const float4* __restrict__ x, float4* __restrict__ out) {
    int t = blockIdx.x * blockDim.x + threadIdx.x;
    if (t >= SLICE) return;

    const float4 tb = g_tab[t];
    const float c0 = tb.x, s0 = tb.y, c1 = tb.z, s1 = tb.w;

    size_t off = (size_t)t;
#pragma unroll 8
    for (int b = 0; b < BH; ++b, off += SLICE) {
        float4 v = __ldg(&x[off]);
        float4 r;
        r.x = c0 * v.x - s0 * v.y;
        r.y = s0 * v.x + c0 * v.y;
        r.z = c1 * v.z - s1 * v.w;
        r.w = s1 * v.z + c1 * v.w;
        out[off] = r;
    }
}

// ---------------------------------------------------------------------------
// Entry point. Identify x vs token_positions by element count (robust to
// input ordering): x has 67108864 elements, positions 4096.
// ---------------------------------------------------------------------------
extern "C" void kernel_launch(void* const* d_in, const int* in_sizes, int n_in,
                              void* d_out, int out_size) {
    const void* xp  = d_in[0];
    const void* pp  = (n_in > 1) ? d_in[1] : d_in[0];
    if (n_in > 1 && in_sizes[0] < in_sizes[1]) {
        xp = d_in[1];
        pp = d_in[0];
    }
    const float4* x = (const float4*)xp;
    float4* out = (float4*)d_out;

    const int tab_threads = SEQ * F4_ROW;               // 131072
    rope_build_table<<<(tab_threads + 255) / 256, 256>>>(pp);
    rope_apply<<<(SLICE + 255) / 256, 256>>>(x, out);
}

// round 7
// speedup vs baseline: 1.1714x; 1.1714x over previous
#include <cuda_runtime.h>
#include <cuda_bf16.h>
#include <math.h>

// Problem shape (fixed by the dataset): x = [4, 32, 4096, 128] fp32.
#define SEQ     4096
#define HDIM    128
#define HALF    (HDIM / 2)          // 64 rotation pairs per row
#define F4_ROW  (HDIM / 4)          // 32 float4 per row (2 pairs per float4)
#define BH      (4 * 32)            // 128 batch*head slices
#define SLICE   (SEQ * F4_ROW)      // float4 per bh-slice = 131072
#define SPLIT   2                   // bh-loop split -> 2x threads, 2x MLP
#define BH_PER  (BH / SPLIT)        // 64 bh iterations per thread
#define BATCH   8                   // loads in flight per thread

// ---------------------------------------------------------------------------
// Position loader with dtype sniffing (reference says int64; harness may have
// materialized int32/float32). Positions are small non-negative ints.
// ---------------------------------------------------------------------------
__device__ __forceinline__ double load_pos(const void* p, int s) {
    const unsigned int* w = (const unsigned int*)p;
    bool hi_zero = (w[1] == 0u) & (w[3] == 0u) & (w[5] == 0u) & (w[7] == 0u);
    bool lo_some = (w[0] | w[2] | w[4] | w[6]) != 0u;
    if (hi_zero && (lo_some || (w[8] | w[9]) == 0u)) {
        return (double)((const long long*)p)[s];
    }
    bool small_ints = (w[1] < (1u << 24)) & (w[2] < (1u << 24)) &
                      (w[3] < (1u << 24));
    if (small_ints) return (double)((const int*)p)[s];
    return (double)((const float*)p)[s];
}

__device__ __forceinline__ float reduce_2pi(double a) {
    const double INV_2PI = 0.15915494309189535;
    const double TWO_PI  = 6.283185307179586;
    double k = rint(a * INV_2PI);
    return (float)(a - k * TWO_PI);
}

// ---------------------------------------------------------------------------
// Fused kernel: each thread owns one float4 column position (t in [0,SLICE))
// and BH_PER bh-slices. Trig computed once per thread (angle in double with
// 2*pi range reduction -> beats the fp32 reference's own trig error).
// First load batch is issued BEFORE the trig so FP64 hides under memory.
// ---------------------------------------------------------------------------
__global__ __launch_bounds__(256) void rope_fused(
    const float4* __restrict__ x, float4* __restrict__ out,
    const void* __restrict__ pos) {
    int t = blockIdx.x * blockDim.x + threadIdx.x;   // 0..SLICE-1
    int s = t >> 5;          // seq index
    int j = t & 31;          // float4 within row -> pairs 2j, 2j+1

    size_t off = (size_t)blockIdx.y * (size_t)BH_PER * SLICE + (size_t)t;

    // Prefetch batch 0 (independent of trig).
    float4 v[BATCH];
#pragma unroll
    for (int k = 0; k < BATCH; ++k)
        v[k] = __ldcs(&x[off + (size_t)k * SLICE]);

    // Per-thread trig (hidden under the loads above).
    double p = load_pos(pos, s);
    const double LOG2_THETA = 13.287712379549449;   // log2(10000)
    double f0 = exp2(-((double)(2 * j)     / (double)HALF) * LOG2_THETA);
    double f1 = exp2(-((double)(2 * j + 1) / (double)HALF) * LOG2_THETA);
    float a0 = reduce_2pi(p * f0);
    float a1 = reduce_2pi(p * f1);
    float s0, c0, s1, c1;
    sincosf(a0, &s0, &c0);
    sincosf(a1, &s1, &c1);

#pragma unroll
    for (int bb = 0; bb < BH_PER / BATCH; ++bb) {
        // Rotate + store current batch.
#pragma unroll
        for (int k = 0; k < BATCH; ++k) {
            float4 r;
            r.x = c0 * v[k].x - s0 * v[k].y;
            r.y = s0 * v[k].x + c0 * v[k].y;
            r.z = c1 * v[k].z - s1 * v[k].w;
            r.w = s1 * v[k].z + c1 * v[k].w;
            __stcs(&out[off + (size_t)k * SLICE], r);
        }
        off += (size_t)BATCH * SLICE;
        // Prefetch next batch.
        if (bb + 1 < BH_PER / BATCH) {
#pragma unroll
            for (int k = 0; k < BATCH; ++k)
                v[k] = __ldcs(&x[off + (size_t)k * SLICE]);
        }
    }
}

// ---------------------------------------------------------------------------
// Entry point. Identify x vs token_positions by element count (robust to
// input ordering): x has 67108864 elements, positions 4096.
// ---------------------------------------------------------------------------
extern "C" void kernel_launch(void* const* d_in, const int* in_sizes, int n_in,
                              void* d_out, int out_size) {
    const void* xp = d_in[0];
    const void* pp = (n_in > 1) ? d_in[1] : d_in[0];
    if (n_in > 1 && in_sizes[0] < in_sizes[1]) {
        xp = d_in[1];
        pp = d_in[0];
    }
    const float4* x = (const float4*)xp;
    float4* out = (float4*)d_out;

    dim3 grid(SLICE / 256, SPLIT);
    rope_fused<<<grid, 256>>>(x, out, pp);
}